// round 5
// baseline (speedup 1.0000x reference)
#include <cuda_runtime.h>
#include <math.h>

#define BATCH 8
#define HH 720
#define WW 1280
#define HW (HH * WW)
#define NPIX (BATCH * HW)

#define CB 2                    // batches per chunk
#define NCHUNK (BATCH / CB)     // 4 chunks
#define CHUNK_PIX (CB * HW)     // 1,843,200 pixels per chunk

// One reusable accumulator buffer (29.5 MB) — stays L2-resident.
// Invariant: all-zero at kernel_launch entry and exit.
// (BSS zero-init covers the very first call; normalize_kernel re-zeroes.)
__device__ float4 g_acc[CHUNK_PIX];

// ---------------------------------------------------------------------------
// Scatter one chunk (CB batches). One thread per source pixel; 4 vector
// reductions (one per bilinear corner) into the L2-resident chunk buffer.
// ---------------------------------------------------------------------------
__device__ __forceinline__ void red_add_v4(float4* addr, float a, float b, float c) {
    asm volatile(
        "red.global.add.v4.f32 [%0], {%1, %2, %3, %4};"
        :: "l"(addr), "f"(a), "f"(b), "f"(c), "f"(0.0f)
        : "memory");
}

__global__ void scatter_kernel(const float* __restrict__ flow,
                               const float* __restrict__ depth,
                               int chunk) {
    int i = blockIdx.x * blockDim.x + threadIdx.x;   // [0, CHUNK_PIX)
    if (i >= CHUNK_PIX) return;

    int bl = i / HW;                 // local batch within chunk
    int p  = i - bl * HW;
    int y  = p / WW;
    int x  = p - y * WW;

    int bg = chunk * CB + bl;        // global batch

    const float* fbase = flow + (size_t)bg * 2 * HW;
    float fx = fbase[p];
    float fy = fbase[HW + p];
    float d  = depth[(size_t)bg * HW + p];

    float x2 = (float)x + fx;
    float y2 = (float)y + fy;

    if (!(x2 >= 0.f && x2 <= (float)(WW - 1) &&
          y2 >= 0.f && y2 <= (float)(HH - 1)))
        return;

    int xL = (int)floorf(x2);
    int yT = (int)floorf(y2);
    int xR = min(xL + 1, WW - 1);
    int yB = min(yT + 1, HH - 1);

    float wx = -fx * d;
    float wy = -fy * d;

    int base = bl * HW;
    int rT = base + yT * WW;
    int rB = base + yB * WW;

    red_add_v4(&g_acc[rT + xL], d, wx, wy);
    red_add_v4(&g_acc[rT + xR], d, wx, wy);
    red_add_v4(&g_acc[rB + xL], d, wx, wy);
    red_add_v4(&g_acc[rB + xR], d, wx, wy);
}

// ---------------------------------------------------------------------------
// Normalize one chunk: read accumulator (L2 hit), write output, and restore
// the all-zero invariant in place (L2-hit stores, overwritten by next chunk's
// atomics before any eviction matters).
// ---------------------------------------------------------------------------
__global__ void normalize_kernel(float* __restrict__ out, int chunk) {
    int i = blockIdx.x * blockDim.x + threadIdx.x;   // [0, CHUNK_PIX)
    if (i >= CHUNK_PIX) return;

    float4 a = g_acc[i];
    g_acc[i] = make_float4(0.f, 0.f, 0.f, 0.f);      // restore invariant

    float ox = 0.f, oy = 0.f;
    if (a.x > 0.f) {
        float inv = 1.f / a.x;
        ox = a.y * inv;
        oy = a.z * inv;
    }

    int bl = i / HW;
    int p  = i - bl * HW;
    int bg = chunk * CB + bl;

    float* obase = out + (size_t)bg * 2 * HW;
    obase[p]      = ox;
    obase[HW + p] = oy;
}

extern "C" void kernel_launch(void* const* d_in, const int* in_sizes, int n_in,
                              void* d_out, int out_size) {
    const float* flow  = (const float*)d_in[0];   // (B, 2, H, W)
    const float* depth = (const float*)d_in[1];   // (B, 1, H, W)
    float* out = (float*)d_out;                   // (B, 2, H, W)

    (void)in_sizes; (void)n_in; (void)out_size;

    const int threads = 256;
    const int blocks = CHUNK_PIX / threads;       // 7200

    for (int c = 0; c < NCHUNK; c++) {
        scatter_kernel<<<blocks, threads>>>(flow, depth, c);
        normalize_kernel<<<blocks, threads>>>(out, c);
    }
}

// round 6
// speedup vs baseline: 1.4781x; 1.4781x over previous
#include <cuda_runtime.h>
#include <math.h>

#define BATCH 8
#define HH 720
#define WW 1280
#define HW (HH * WW)
#define NPIX (BATCH * HW)

// Packed accumulator: (cnt, ox, oy, pad). 16B aligned for red.global.add.v4.f32.
// 118 MB — nearly fits the 126 MB L2; streaming hints on all other traffic
// keep it resident from zero -> scatter -> normalize.
__device__ float4 g_acc[NPIX];

// ---------------------------------------------------------------------------
// Kernel 1: zero the accumulator plane. One float4 per thread per iteration
// (fully coalesced; also primes L2 with accumulator lines).
// ---------------------------------------------------------------------------
__global__ void zero_kernel() {
    float4 z = make_float4(0.f, 0.f, 0.f, 0.f);
    int stride = gridDim.x * blockDim.x;
    for (int k = blockIdx.x * blockDim.x + threadIdx.x; k < NPIX; k += stride) {
        g_acc[k] = z;
    }
}

// ---------------------------------------------------------------------------
// Kernel 2: scatter. One thread per source pixel; 4 vector reductions
// (one per bilinear corner). Inputs read with evict-first (.cs) hints so the
// 88.5 MB of single-use streaming reads don't evict accumulator lines.
// ---------------------------------------------------------------------------
__device__ __forceinline__ void red_add_v4(float4* addr, float a, float b, float c) {
    asm volatile(
        "red.global.add.v4.f32 [%0], {%1, %2, %3, %4};"
        :: "l"(addr), "f"(a), "f"(b), "f"(c), "f"(0.0f)
        : "memory");
}

__global__ void scatter_kernel(const float* __restrict__ flow,
                               const float* __restrict__ depth) {
    int i = blockIdx.x * blockDim.x + threadIdx.x;
    if (i >= NPIX) return;

    int b = i / HW;
    int p = i - b * HW;
    int y = p / WW;
    int x = p - y * WW;

    const float* fbase = flow + (size_t)b * 2 * HW;
    float fx = __ldcs(fbase + p);
    float fy = __ldcs(fbase + HW + p);
    float d  = __ldcs(depth + i);

    float x2 = (float)x + fx;
    float y2 = (float)y + fy;

    if (!(x2 >= 0.f && x2 <= (float)(WW - 1) &&
          y2 >= 0.f && y2 <= (float)(HH - 1)))
        return;

    int xL = (int)floorf(x2);
    int yT = (int)floorf(y2);
    int xR = min(xL + 1, WW - 1);
    int yB = min(yT + 1, HH - 1);

    float wx = -fx * d;
    float wy = -fy * d;

    int base = b * HW;
    int rT = base + yT * WW;
    int rB = base + yB * WW;

    red_add_v4(&g_acc[rT + xL], d, wx, wy);
    red_add_v4(&g_acc[rT + xR], d, wx, wy);
    red_add_v4(&g_acc[rB + xL], d, wx, wy);
    red_add_v4(&g_acc[rB + xR], d, wx, wy);
}

// ---------------------------------------------------------------------------
// Kernel 3: normalize + write (B, 2, H, W). Accumulator reads should be L2
// hits; output written with streaming (.cs) stores (single-use, no-allocate).
// Two independent pixels per thread for MLP.
// ---------------------------------------------------------------------------
__global__ void normalize_kernel(float* __restrict__ out) {
    int tid = blockIdx.x * blockDim.x + threadIdx.x;
    int stride = gridDim.x * blockDim.x;          // = NPIX/2 exactly

    int i0 = tid;
    int i1 = tid + stride;

    float4 a0 = g_acc[i0];
    float4 a1 = g_acc[i1];

    float ox0 = 0.f, oy0 = 0.f;
    if (a0.x > 0.f) { float inv = 1.f / a0.x; ox0 = a0.y * inv; oy0 = a0.z * inv; }
    float ox1 = 0.f, oy1 = 0.f;
    if (a1.x > 0.f) { float inv = 1.f / a1.x; ox1 = a1.y * inv; oy1 = a1.z * inv; }

    int b0 = i0 / HW, p0 = i0 - b0 * HW;
    int b1 = i1 / HW, p1 = i1 - b1 * HW;

    float* ob0 = out + (size_t)b0 * 2 * HW;
    float* ob1 = out + (size_t)b1 * 2 * HW;
    __stcs(ob0 + p0,      ox0);
    __stcs(ob0 + HW + p0, oy0);
    __stcs(ob1 + p1,      ox1);
    __stcs(ob1 + HW + p1, oy1);
}

extern "C" void kernel_launch(void* const* d_in, const int* in_sizes, int n_in,
                              void* d_out, int out_size) {
    const float* flow  = (const float*)d_in[0];   // (B, 2, H, W)
    const float* depth = (const float*)d_in[1];   // (B, 1, H, W)
    float* out = (float*)d_out;                   // (B, 2, H, W)

    (void)in_sizes; (void)n_in; (void)out_size;

    const int threads = 256;

    zero_kernel<<<1480, threads>>>();

    int blocks = (NPIX + threads - 1) / threads;
    scatter_kernel<<<blocks, threads>>>(flow, depth);

    int nblocks = (NPIX / 2) / threads;           // 14400
    normalize_kernel<<<nblocks, threads>>>(out);
}